// round 12
// baseline (speedup 1.0000x reference)
#include <cuda_runtime.h>
#include <cuda_bf16.h>

#define NPTS 1024
#define NG   27
#define NM   128
#define CUT2 25.0f
#define FULL 0xffffffffu
#define PPB  8

// Pair-centric minimal-image, shared-staged output. 8 points/block,
// 4 warps/point (1024 thr, grid=128, single wave). Dynamic smem (61.7 KB).
//  P1: each thread evaluates 8 pairs; only the nearest image can hit
//      (cutoff < box/2). Hits -> per-cell bitmask (atomicOr) + count.
//  scan: every warp redundantly scans the 27 counts in registers (shfl).
//  P2: lane l owns mask word pb=l; shfl exclusive scan + ffs emit into
//      shared rows pre-filled with pad values.
//  flush: coalesced float4 stores.
// OUTPUT FLOAT32: [1024*128] neigh | [1024*128*3] cells | [1] actual_max

// dynamic smem layout (bytes)
#define OFF_S4     0                          // float4[1024]        16384
#define OFF_NEIGH  16384                      // float[PPB][128]      4096
#define OFF_CELL   20480                      // float[PPB][384]     12288
#define OFF_MASK   32768                      // uint[PPB][NG*32]    27648
#define OFF_CNT    60416                      // int[PPB][NG]          864
#define OFF_CLX    61280                      // float[NG]             108
#define OFF_CLY    61388
#define OFF_CLZ    61496
#define OFF_LUT    61604                      // int[NG]               108
#define SMEM_TOTAL 61712

__global__ __launch_bounds__(1024) void periodic_neigh_kernel(
    const float* __restrict__ pos,     // (1024,3)
    const float* __restrict__ gp,      // (27,3) grid_points (== 20*cl)
    const int*   __restrict__ cl,      // (27,3) cell_list
    float* __restrict__ out)
{
    extern __shared__ __align__(16) char smem[];
    float4*   s4     = (float4*)(smem + OFF_S4);
    float*    sneigh = (float*)(smem + OFF_NEIGH);   // [PPB][NM]
    float*    scell  = (float*)(smem + OFF_CELL);    // [PPB][NM*3]
    unsigned* smask  = (unsigned*)(smem + OFF_MASK); // [PPB][NG*32]
    int*      scnt   = (int*)(smem + OFF_CNT);       // [PPB][NG]
    float*    clxf   = (float*)(smem + OFF_CLX);
    float*    clyf   = (float*)(smem + OFF_CLY);
    float*    clzf   = (float*)(smem + OFF_CLZ);
    int*      lut    = (int*)(smem + OFF_LUT);

    const int tid  = threadIdx.x;
    const int lane = tid & 31;
    const int warp = tid >> 5;
    const int pt   = warp >> 2;
    const int w    = warp & 3;
    const int t128 = tid & 127;
    const int i    = blockIdx.x * PPB + pt;
    (void)gp;

    // zero masks (uint4) + counts
    {
        uint4 z = make_uint4(0u, 0u, 0u, 0u);
        uint4* m4 = (uint4*)smask;
        #pragma unroll
        for (int v = tid; v < (PPB * NG * 32) / 4; v += 1024) m4[v] = z;
    }
    if (tid < PPB * NG) scnt[tid] = 0;

    // stage positions: exactly one per thread
    s4[tid] = make_float4(pos[3 * tid], pos[3 * tid + 1], pos[3 * tid + 2], 0.0f);

    // tables
    if (tid < NG) {
        const int a = cl[3 * tid], b = cl[3 * tid + 1], c = cl[3 * tid + 2];
        clxf[tid] = (float)a; clyf[tid] = (float)b; clzf[tid] = (float)c;
        lut[(a + 1) * 9 + (b + 1) * 3 + (c + 1)] = tid;
    }
    __syncthreads();

    // pre-fill output rows with pad values:
    // neigh = -1; cells = cell_list[NG-1] (jnp.take(-1) wraps to the end)
    {
        const float fx = clxf[NG - 1], fy = clyf[NG - 1], fz = clzf[NG - 1];
        sneigh[pt * NM + t128] = -1.0f;
        scell[pt * NM * 3 + t128 * 3 + 0] = fx;
        scell[pt * NM * 3 + t128 * 3 + 1] = fy;
        scell[pt * NM * 3 + t128 * 3 + 2] = fz;
    }

    const float4 qi = s4[i];

    // ---- Phase 1: 8 pairs per thread, nearest-image test ----
    #pragma unroll
    for (int k = 0; k < 8; k++) {
        const int p  = k * 128 + t128;
        const int pb = p >> 5;
        const float4 q = s4[p];
        const float sxf = rintf((q.x - qi.x) * 0.05f);   // exact in {-1,0,1}
        const float syf = rintf((q.y - qi.y) * 0.05f);
        const float szf = rintf((q.z - qi.z) * 0.05f);
        // reference arithmetic: (gx + xp) - xi with gx = -20*s (exact)
        const float dx = (-20.0f * sxf + q.x) - qi.x;
        const float dy = (-20.0f * syf + q.y) - qi.y;
        const float dz = (-20.0f * szf + q.z) - qi.z;
        const float d2 = dx * dx + dy * dy + dz * dz;
        if (d2 < CUT2) {
            const int idx = (int)(13.0f - (sxf * 9.0f + syf * 3.0f + szf));
            const int g = lut[idx];
            atomicOr(&smask[pt * NG * 32 + (g << 5) + pb], 1u << lane);
            atomicAdd(&scnt[pt * NG + g], 1);
        }
    }
    __syncthreads();

    // ---- per-warp redundant scan of the 27 counts (registers only) ----
    int vs = (lane < NG) ? scnt[pt * NG + lane] : 0;
    #pragma unroll
    for (int d = 1; d < 32; d <<= 1) {
        const int n = __shfl_up_sync(FULL, vs, d);
        if (lane >= d) vs += n;
    }
    const int total = __shfl_sync(FULL, vs, NG - 1);

    // ---- Phase 2: lane l owns pb=l; shfl scan -> base; ffs emit to SMEM ----
    for (int g = w; g < NG; g += 4) {
        const int inc  = __shfl_sync(FULL, vs, g);
        const int base = (g == 0) ? 0 : __shfl_sync(FULL, vs, g - 1);
        if (inc == base || base >= NM) continue;
        unsigned m = smask[pt * NG * 32 + (g << 5) + lane];
        const int c = __popc(m);
        int v = c;
        #pragma unroll
        for (int d = 1; d < 32; d <<= 1) {
            const int n = __shfl_up_sync(FULL, v, d);
            if (lane >= d) v += n;
        }
        int slot = base + v - c;                  // exclusive prefix
        if (m && slot < NM) {
            const float cx = clxf[g], cy = clyf[g], cz = clzf[g];
            const int pbase = lane * 32;
            do {
                const int b = __ffs(m) - 1;
                m &= m - 1;
                sneigh[pt * NM + slot] = (float)(pbase + b);
                const int cb = pt * NM * 3 + slot * 3;
                scell[cb + 0] = cx;
                scell[cb + 1] = cy;
                scell[cb + 2] = cz;
                slot++;
            } while (m && slot < NM);
        }
    }
    __syncthreads();

    // ---- flush: coalesced float4 stores (1024 f4 over 1024 threads) ----
    float4* __restrict__ neigh4 = (float4*)out;                  // 1024*32
    float4* __restrict__ cell4  = (float4*)(out + NPTS * NM);    // 1024*96
    float*  __restrict__ amax   = out + NPTS * NM * 4;

    if (tid < PPB * (NM / 4)) {                   // 256 f4 of neigh
        const int pt2 = tid >> 5, q = tid & 31;
        neigh4[(blockIdx.x * PPB + pt2) * (NM / 4) + q] =
            ((const float4*)(sneigh + pt2 * NM))[q];
    } else {                                      // 768 f4 of cells
        const int u = tid - PPB * (NM / 4);
        const int pt2 = u / 96, q = u - pt2 * 96;
        cell4[(blockIdx.x * PPB + pt2) * 96 + q] =
            ((const float4*)(scell + pt2 * NM * 3))[q];
    }

    // actual_max (untruncated); int-view atomicMax == float max for
    // non-negative floats; poison 0xAAAAAAAA is negative and always loses.
    if (w == 0 && lane == 0)
        atomicMax((int*)amax, __float_as_int((float)total));
}

extern "C" void kernel_launch(void* const* d_in, const int* in_sizes, int n_in,
                              void* d_out, int out_size) {
    const float* positions   = (const float*)d_in[0];
    const float* grid_points = (const float*)d_in[1];
    const int*   cell_list   = (const int*)d_in[2];
    (void)in_sizes; (void)n_in; (void)out_size;

    // Idempotent, deterministic, not a stream op -> graph-capture safe.
    cudaFuncSetAttribute(periodic_neigh_kernel,
                         cudaFuncAttributeMaxDynamicSharedMemorySize,
                         SMEM_TOTAL);

    periodic_neigh_kernel<<<NPTS / PPB, 1024, SMEM_TOTAL>>>(
        positions, grid_points, cell_list, (float*)d_out);
}